// round 15
// baseline (speedup 1.0000x reference)
#include <cuda_runtime.h>
#include <math.h>
#include <float.h>
#include <stdint.h>

// Problem constants
#define Bv 2
#define Nv 2048
#define Cv 1024
#define Hv 16
#define Dv 64
#define BHv (Bv*Hv)        // 32
#define MROWS (Bv*Nv)      // 4096
#define C3 (3*Cv)          // 3072

// Static device scratch (allocation-free rule)
__device__ float g_q[BHv*Nv*Dv];            // [b,h,n,d] (d interleaved perm8 for flash)
__device__ float g_k[BHv*Nv*Dv];            // [b,h,n,d] (d interleaved perm8)
__device__ float g_v[BHv*Nv*Dv];            // [b,h,d,n] transposed, natural token order
__device__ float g_attn[MROWS*Cv];          // [b*n, h*d], tf32-rounded + perm32 K-layout
__device__ float g_xr[MROWS*Cv];            // x, tf32-rounded + perm32
__device__ float g_wqkvr[C3*Cv];            // w_qkv, rounded + perm32
__device__ float g_wprojr[Cv*Cv];           // w_proj, rounded + perm32
__device__ int   g_maskflag;

// ---------------- tf32 helpers ----------------
__device__ __forceinline__ float f2tf32(float x) {
    uint32_t u;
    asm("cvt.rna.tf32.f32 %0, %1;" : "=r"(u) : "f"(x));
    return __uint_as_float(u);
}

__device__ __forceinline__ void mma_tf32(float* c, const uint32_t* a, uint32_t b0, uint32_t b1) {
    asm volatile(
        "mma.sync.aligned.m16n8k8.row.col.f32.tf32.tf32.f32 "
        "{%0,%1,%2,%3}, {%4,%5,%6,%7}, {%8,%9}, {%0,%1,%2,%3};\n"
        : "+f"(c[0]), "+f"(c[1]), "+f"(c[2]), "+f"(c[3])
        : "r"(a[0]), "r"(a[1]), "r"(a[2]), "r"(a[3]), "r"(b0), "r"(b1));
}

__device__ __forceinline__ void cp16(uint32_t dst, const void* src) {
    asm volatile("cp.async.cg.shared.global [%0], [%1], 16;\n" :: "r"(dst), "l"(src));
}

// perm8 (flash q/k layout): orig j in 8-block -> pos ((j&3)<<1)|(j>>2)
__device__ __forceinline__ int perm8(int j) { return ((j & 3) << 1) | (j >> 2); }
// perm32 (GEMM operand layout): within 32-block, orig col o = 8j + t (t=o&7, j=(o>>3)&3)
// -> pos ((t&3)<<3) + (j<<1) + (t>>2). One float4 per row covers a kk-pair.
__device__ __forceinline__ int perm32(int o) {
    int t = o & 7, j = (o >> 3) & 3;
    return (o & ~31) + ((t & 3) << 3) + (j << 1) + (t >> 2);
}

// ---------------- pre-round + perm32 K-interleave: one thread per 32-col block ----------------
__global__ void round_perm_kernel(const float4* __restrict__ in, float4* __restrict__ out, int n32)
{
    for (int i = blockIdx.x * blockDim.x + threadIdx.x; i < n32; i += gridDim.x * blockDim.x) {
        float s[32];
        #pragma unroll
        for (int j = 0; j < 8; j++) {
            float4 t = in[i * 8 + j];
            s[j*4+0] = f2tf32(t.x); s[j*4+1] = f2tf32(t.y);
            s[j*4+2] = f2tf32(t.z); s[j*4+3] = f2tf32(t.w);
        }
        #pragma unroll
        for (int tp = 0; tp < 4; tp++) {
            out[i * 8 + 2*tp]     = make_float4(s[tp],      s[tp + 4],  s[tp + 8],  s[tp + 12]);
            out[i * 8 + 2*tp + 1] = make_float4(s[tp + 16], s[tp + 20], s[tp + 24], s[tp + 28]);
        }
    }
}

// ---------------- Epilogue policies (warp-level store) ----------------
// acc layout: acc[mt][nt][r] -> row (bm + wm*32 + mt*16 + group) for r=0,1,
//             row +8 for r=2,3; col (bn + wn*64 + nt*8 + tg*2 + (r&1)).
struct EpiQKV {
    float *q, *k, *v;
    const float *qg, *qb, *kg, *kb;
    __device__ __forceinline__ void store(int bz, int bm, int bn, int wm, int wn,
                                          int group, int tg,
                                          const float (&acc)[2][8][4]) const {
        const int ncol0 = bn + wn * 64;      // aligned 64-block: one (which, head)
        const int which = ncol0 >> 10;
        const int h     = (ncol0 & 1023) >> 6;
        if (which == 2) {
            // ---- V: transposed [b,h][d][n], natural token order, tf32 ----
            #pragma unroll
            for (int mt = 0; mt < 2; mt++) {
                int m0 = bm + wm * 32 + mt * 16 + group;
                int b0 = m0 >> 11, t0 = m0 & 2047;
                int m1 = m0 + 8;
                int b1 = m1 >> 11, t1 = m1 & 2047;
                float* base0 = v + (((size_t)(b0 * Hv + h) * Dv) << 11) + t0;
                float* base1 = v + (((size_t)(b1 * Hv + h) * Dv) << 11) + t1;
                #pragma unroll
                for (int nt = 0; nt < 8; nt++) {
                    int dd = nt * 8 + tg * 2;
                    base0[(size_t)dd << 11]       = f2tf32(acc[mt][nt][0]);
                    base0[(size_t)(dd + 1) << 11] = f2tf32(acc[mt][nt][1]);
                    base1[(size_t)dd << 11]       = f2tf32(acc[mt][nt][2]);
                    base1[(size_t)(dd + 1) << 11] = f2tf32(acc[mt][nt][3]);
                }
            }
        } else {
            // ---- q/k: fused LayerNorm over the 64 cols (quad-distributed), perm8 store ----
            const float* G  = which ? kg : qg;
            const float* Bt = which ? kb : qb;
            float* dst = which ? k : q;
            const int pa = perm8(2 * tg), pb = perm8(2 * tg + 1);
            #pragma unroll
            for (int mt = 0; mt < 2; mt++) {
                float sA = 0.f, sB = 0.f;
                #pragma unroll
                for (int nt = 0; nt < 8; nt++) {
                    sA += acc[mt][nt][0] + acc[mt][nt][1];
                    sB += acc[mt][nt][2] + acc[mt][nt][3];
                }
                sA += __shfl_xor_sync(0xFFFFFFFFu, sA, 1);
                sA += __shfl_xor_sync(0xFFFFFFFFu, sA, 2);
                sB += __shfl_xor_sync(0xFFFFFFFFu, sB, 1);
                sB += __shfl_xor_sync(0xFFFFFFFFu, sB, 2);
                float muA = sA * (1.f/64.f), muB = sB * (1.f/64.f);
                float vA = 0.f, vB = 0.f;
                #pragma unroll
                for (int nt = 0; nt < 8; nt++) {
                    float d0 = acc[mt][nt][0] - muA, d1 = acc[mt][nt][1] - muA;
                    float d2 = acc[mt][nt][2] - muB, d3 = acc[mt][nt][3] - muB;
                    vA += d0*d0 + d1*d1;
                    vB += d2*d2 + d3*d3;
                }
                vA += __shfl_xor_sync(0xFFFFFFFFu, vA, 1);
                vA += __shfl_xor_sync(0xFFFFFFFFu, vA, 2);
                vB += __shfl_xor_sync(0xFFFFFFFFu, vB, 1);
                vB += __shfl_xor_sync(0xFFFFFFFFu, vB, 2);
                float invA = rsqrtf(vA * (1.f/64.f) + 1e-5f);
                float invB = rsqrtf(vB * (1.f/64.f) + 1e-5f);

                int m0 = bm + wm * 32 + mt * 16 + group;
                int b0 = m0 >> 11, t0 = m0 & 2047;
                int m1 = m0 + 8;
                int b1 = m1 >> 11, t1 = m1 & 2047;
                float* r0 = dst + (((size_t)(b0 * Hv + h) * Nv + t0) << 6);
                float* r1 = dst + (((size_t)(b1 * Hv + h) * Nv + t1) << 6);
                #pragma unroll
                for (int nt = 0; nt < 8; nt++) {
                    int dd = nt * 8 + tg * 2;
                    float g0 = G[dd], g1 = G[dd + 1];
                    float bt0 = Bt[dd], bt1 = Bt[dd + 1];
                    r0[nt*8 + pa] = f2tf32((acc[mt][nt][0] - muA) * invA * g0 + bt0);
                    r0[nt*8 + pb] = f2tf32((acc[mt][nt][1] - muA) * invA * g1 + bt1);
                    r1[nt*8 + pa] = f2tf32((acc[mt][nt][2] - muB) * invB * g0 + bt0);
                    r1[nt*8 + pb] = f2tf32((acc[mt][nt][3] - muB) * invB * g1 + bt1);
                }
            }
        }
    }
};

struct EpiOut {
    float* out;
    const float* bias;
    __device__ __forceinline__ void store(int bz, int bm, int bn, int wm, int wn,
                                          int group, int tg,
                                          const float (&acc)[2][8][4]) const {
        #pragma unroll
        for (int mt = 0; mt < 2; mt++) {
            int r0 = bm + wm * 32 + mt * 16 + group;
            #pragma unroll
            for (int nt = 0; nt < 8; nt++) {
                int c0 = bn + wn * 64 + nt * 8 + tg * 2;
                out[(size_t)r0 * Cv + c0]           = acc[mt][nt][0] + bias[c0];
                out[(size_t)r0 * Cv + c0 + 1]       = acc[mt][nt][1] + bias[c0 + 1];
                out[(size_t)(r0 + 8) * Cv + c0]     = acc[mt][nt][2] + bias[c0];
                out[(size_t)(r0 + 8) * Cv + c0 + 1] = acc[mt][nt][3] + bias[c0 + 1];
            }
        }
    }
};

// ============ async tf32 GEMM, TN, operands pre-rounded + perm32 K-layout ============
// C = A(MxK,rm) * B(NxK,rm)^T.  BM=BN=128, BK=32, 256 threads, 2-stage cp.async.
// GP=36: LDS.128 quarter-warp banks = (4g + 8tg + 4p) mod 32 -> conflict-free.
#define GP 36                       // smem pitch (floats)
#define GASZ (128*GP)               // one stage of one operand (4608 floats)
template<class Epi>
__global__ void __launch_bounds__(256, 2)
gemm_tc_async(const float* __restrict__ A, const float* __restrict__ B,
              int K, long long sA, long long sB, Epi epi)
{
    constexpr int BM = 128, BN = 128, BK = 32, WM = 32, WN = 64;
    constexpr int WARPS_N = BN / WN;          // 2
    constexpr int MT = WM / 16, NT = WN / 8;  // 2, 8

    extern __shared__ float sg[];             // [A0][A1][B0][B1], each GASZ floats
    const int bz = blockIdx.z;
    A += (long long)bz * sA + (long long)blockIdx.y * BM * K;
    B += (long long)bz * sB + (long long)blockIdx.x * BN * K;
    const int tid  = threadIdx.x;
    const int warp = tid >> 5, lane = tid & 31;
    const int wm = warp / WARPS_N, wn = warp % WARPS_N;
    const int group = lane >> 2, tg = lane & 3;
    uint32_t sb = (uint32_t)__cvta_generic_to_shared(sg);

    auto prefetch = [&](int k0, int s) {
        #pragma unroll
        for (int j = 0; j < 4; j++) {
            int i = tid + j * 256;
            int m = i >> 3, kv = i & 7;       // 128 rows x 8 float4
            cp16(sb + (uint32_t)((s * GASZ + m * GP + kv * 4) * 4),
                 A + (long long)m * K + k0 + kv * 4);
            cp16(sb + (uint32_t)(((2 + s) * GASZ + m * GP + kv * 4) * 4),
                 B + (long long)m * K + k0 + kv * 4);
        }
        asm volatile("cp.async.commit_group;\n" ::: "memory");
    };

    float acc[MT][NT][4];
    #pragma unroll
    for (int i = 0; i < MT; i++)
        #pragma unroll
        for (int j = 0; j < NT; j++)
            #pragma unroll
            for (int r = 0; r < 4; r++) acc[i][j][r] = 0.f;

    const int nk = K / BK;
    prefetch(0, 0);
    prefetch(BK, 1);

    for (int kt = 0; kt < nk; kt++) {
        const int s = kt & 1;
        if (kt < nk - 1) asm volatile("cp.async.wait_group 1;\n" ::: "memory");
        else             asm volatile("cp.async.wait_group 0;\n" ::: "memory");
        __syncthreads();

        const float* As = sg + s * GASZ;
        const float* Bs = sg + (2 + s) * GASZ;

        // two kk-pairs per BK=32; each float4 covers a pair of k8 fragments
        #pragma unroll
        for (int p = 0; p < 2; p++) {
            float4 a0[MT], a1[MT];
            #pragma unroll
            for (int mt = 0; mt < MT; mt++) {
                int r = wm * WM + mt * 16 + group;
                a0[mt] = *(const float4*)(As + r * GP + tg * 8 + 4 * p);
                a1[mt] = *(const float4*)(As + (r + 8) * GP + tg * 8 + 4 * p);
            }
            #pragma unroll
            for (int nt = 0; nt < NT; nt++) {
                int c = wn * WN + nt * 8 + group;
                float4 bq = *(const float4*)(Bs + c * GP + tg * 8 + 4 * p);
                #pragma unroll
                for (int mt = 0; mt < MT; mt++) {
                    uint32_t af0[4] = { __float_as_uint(a0[mt].x), __float_as_uint(a1[mt].x),
                                        __float_as_uint(a0[mt].y), __float_as_uint(a1[mt].y) };
                    mma_tf32(acc[mt][nt], af0, __float_as_uint(bq.x), __float_as_uint(bq.y));
                    uint32_t af1[4] = { __float_as_uint(a0[mt].z), __float_as_uint(a1[mt].z),
                                        __float_as_uint(a0[mt].w), __float_as_uint(a1[mt].w) };
                    mma_tf32(acc[mt][nt], af1, __float_as_uint(bq.z), __float_as_uint(bq.w));
                }
            }
        }
        __syncthreads();
        if (kt + 2 < nk) prefetch((kt + 2) * BK, s);
    }

    epi.store(bz, blockIdx.y * BM, blockIdx.x * BN, wm, wn, group, tg, acc);
}
#define GEMM_SMEM (4*GASZ*4)        // 73728 bytes -> 2 CTAs/SM

// ---------------- mask any-true scan ----------------
__global__ void mask_any_kernel(const uint4* __restrict__ m, int n4, int* flag)
{
    int i = blockIdx.x * blockDim.x + threadIdx.x;
    bool any = false;
    for (; i < n4; i += gridDim.x * blockDim.x) {
        uint4 t = m[i];
        any |= ((t.x | t.y | t.z | t.w) != 0u);
    }
    if (__syncthreads_or(any)) {
        if (threadIdx.x == 0) atomicOr(flag, 1);
    }
}

// ================= fused flash attention =================
// CTA: 128 threads (4 warps, 64 q-rows). KV tile 32 tokens, double-buffered.
// PV uses kv relabeling sigma=perm8: P accumulators feed mma A directly, no shuffles.
#define QR 64
#define KT 32
#define PITCH 72            // Q/K row pitch (floats)
#define VPITCH 40           // V^T row pitch (floats)
#define QTILEF (QR*PITCH)   // 4608
#define KTILEF (KT*PITCH)   // 2304
#define VTILEF (Dv*VPITCH)  // 2560
#define OFF_K0 QTILEF
#define OFF_K1 (QTILEF + KTILEF)
#define OFF_V0 (QTILEF + 2*KTILEF)
#define OFF_V1 (QTILEF + 2*KTILEF + VTILEF)
#define FLASH_SMEM_F (QTILEF + 2*KTILEF + 2*VTILEF)   // 14336 floats = 57344 B

template<bool MASKED>
__global__ void __launch_bounds__(128, 4)
flash_kernel(const float* __restrict__ q, const float* __restrict__ k,
             const float* __restrict__ v, const unsigned char* __restrict__ mask,
             const int* __restrict__ maskflag, float* __restrict__ aout)
{
    const int mf = *maskflag;
    if (MASKED ? (mf == 0) : (mf != 0)) return;   // exactly one instance runs

    extern __shared__ float sm[];
    const int tid  = threadIdx.x;
    const int warp = tid >> 5, lane = tid & 31;
    const int group = lane >> 2, tg = lane & 3;
    const int qtile = blockIdx.x;
    const int bh = blockIdx.y;
    const int bB = bh >> 4, h = bh & 15;

    const float* qbase = q + (size_t)bh * Nv * Dv + (size_t)qtile * QR * Dv;
    const float* kbase = k + (size_t)bh * Nv * Dv;
    const float* vbase = v + (size_t)bh * Nv * Dv;      // [d][n] layout
    uint32_t sbase = (uint32_t)__cvta_generic_to_shared(sm);

    // ---- stage Q tile (pre-scaled by d^-1/2) ----
    #pragma unroll
    for (int i = 0; i < 8; i++) {
        int idx = tid + i * 128;              // 64 rows x 16 float4
        int row = idx >> 4, c4 = (idx & 15) * 4;
        float4 t = *(const float4*)(qbase + row * Dv + c4);
        t.x *= 0.125f; t.y *= 0.125f; t.z *= 0.125f; t.w *= 0.125f;
        *(float4*)(sm + row * PITCH + c4) = t;
    }
    __syncthreads();

    auto prefetch = [&](int t, int b) {
        const float* kb = kbase + (size_t)t * KT * Dv;
        const float* vb = vbase + (size_t)t * KT;       // column block of V^T
        uint32_t kd = sbase + (uint32_t)((b ? OFF_K1 : OFF_K0)) * 4u;
        uint32_t vd = sbase + (uint32_t)((b ? OFF_V1 : OFF_V0)) * 4u;
        #pragma unroll
        for (int i = 0; i < 4; i++) {
            int idx = tid + i * 128;
            {   // K: 32 rows x 16 float4
                int row = idx >> 4, c4 = (idx & 15) * 4;
                cp16(kd + (row * PITCH + c4) * 4, kb + row * Dv + c4);
            }
            {   // V^T: 64 rows x 8 float4
                int row = idx >> 3, c4 = (idx & 7) * 4;
                cp16(vd + (row * VPITCH + c4) * 4, vb + (size_t)row * Nv + c4);
            }
        }
        asm volatile("cp.async.commit_group;\n" ::: "memory");
    };

    prefetch(0, 0);
    prefetch(1, 1);

    // ---- running state ----
    float m0 = -FLT_MAX, m1 = -FLT_MAX, l0 = 0.f, l1 = 0.f;
    float oacc[8][4];
    #pragma unroll
    for (int i = 0; i < 8; i++)
        #pragma unroll
        for (int j = 0; j < 4; j++) oacc[i][j] = 0.f;

    const int NTILES = Nv / KT;               // 64
    const float* Qr0 = sm + (warp * 16 + group) * PITCH + tg * 2;
    const float* Qr1 = Qr0 + 8 * PITCH;

    for (int t = 0; t < NTILES; t++) {
        const int buf = t & 1;
        if (t < NTILES - 1) asm volatile("cp.async.wait_group 1;\n" ::: "memory");
        else                asm volatile("cp.async.wait_group 0;\n" ::: "memory");
        __syncthreads();

        const float* Kb = sm + (buf ? OFF_K1 : OFF_K0);
        const float* Vb = sm + (buf ? OFF_V1 : OFF_V0);

        // ---- S = Q K^T (16 x 32 per warp), LDS.64 fragments ----
        float sacc[4][4];
        #pragma unroll
        for (int nt = 0; nt < 4; nt++)
            #pragma unroll
            for (int r = 0; r < 4; r++) sacc[nt][r] = 0.f;

        #pragma unroll
        for (int kk = 0; kk < 8; kk++) {
            float2 qa = *(const float2*)(Qr0 + kk * 8);
            float2 qb = *(const float2*)(Qr1 + kk * 8);
            uint32_t a[4] = { __float_as_uint(qa.x), __float_as_uint(qb.x),
                              __float_as_uint(qa.y), __float_as_uint(qb.y) };
            #pragma unroll
            for (int nt = 0; nt < 4; nt++) {
                float2 kf = *(const float2*)(Kb + (nt * 8 + group) * PITCH + kk * 8 + tg * 2);
                mma_tf32(sacc[nt], a, __float_as_uint(kf.x), __float_as_uint(kf.y));
            }
        }

        float rs0 = 0.f, rs1 = 0.f;
        if (MASKED) {
            // ---- mask + full online softmax (general path) ----
            const unsigned char* mr0 = mask + ((size_t)(bB * Nv + qtile*QR + warp*16 + group)) * Nv + t * KT;
            const unsigned char* mr1 = mr0 + 8 * Nv;
            #pragma unroll
            for (int nt = 0; nt < 4; nt++) {
                int c = nt * 8 + 2 * tg;
                if (mr0[c])     sacc[nt][0] = -FLT_MAX;
                if (mr0[c + 1]) sacc[nt][1] = -FLT_MAX;
                if (mr1[c])     sacc[nt][2] = -FLT_MAX;
                if (mr1[c + 1]) sacc[nt][3] = -FLT_MAX;
            }
            float mn0 = -FLT_MAX, mn1 = -FLT_MAX;
            #pragma unroll
            for (int nt = 0; nt < 4; nt++) {
                mn0 = fmaxf(mn0, fmaxf(sacc[nt][0], sacc[nt][1]));
                mn1 = fmaxf(mn1, fmaxf(sacc[nt][2], sacc[nt][3]));
            }
            mn0 = fmaxf(mn0, __shfl_xor_sync(0xFFFFFFFFu, mn0, 1));
            mn0 = fmaxf(mn0, __shfl_xor_sync(0xFFFFFFFFu, mn0, 2));
            mn1 = fmaxf(mn1, __shfl_xor_sync(0xFFFFFFFFu, mn1, 1));
            mn1 = fmaxf(mn1, __shfl_xor_sync(0xFFFFFFFFu, mn1, 2));
            float mt0 = fmaxf(m0, mn0), mt1 = fmaxf(m1, mn1);
            #pragma unroll
            for (int nt = 0; nt < 4; nt++) {
                float p0 = __expf(sacc[nt][0] - mt0);
                float p1 = __expf(sacc[nt][1] - mt0);
                float p2 = __expf(sacc[nt][2] - mt1);
                float p3 = __expf(sacc[nt][3] - mt1);
                rs0 += p0 + p1; rs1 += p2 + p3;
                sacc[nt][0] = f2tf32(p0); sacc[nt][1] = f2tf32(p1);
                sacc[nt][2] = f2tf32(p2); sacc[nt][3] = f2tf32(p3);
            }
            rs0 += __shfl_xor_sync(0xFFFFFFFFu, rs0, 1);
            rs0 += __shfl_xor_sync(0xFFFFFFFFu, rs0, 2);
            rs1 += __shfl_xor_sync(0xFFFFFFFFu, rs1, 1);
            rs1 += __shfl_xor_sync(0xFFFFFFFFu, rs1, 2);
            if (__any_sync(0xFFFFFFFFu, (mn0 > m0) | (mn1 > m1))) {
                float a0 = __expf(m0 - mt0), a1 = __expf(m1 - mt1);
                l0 = a0 * l0 + rs0;
                l1 = a1 * l1 + rs1;
                #pragma unroll
                for (int i = 0; i < 8; i++) {
                    oacc[i][0] *= a0; oacc[i][1] *= a0;
                    oacc[i][2] *= a1; oacc[i][3] *= a1;
                }
            } else {
                l0 += rs0; l1 += rs1;
            }
            m0 = mt0; m1 = mt1;
        } else {
            // ---- fixed-max softmax: LN bounds |S| <= 8, exp directly ----
            #pragma unroll
            for (int nt = 0; nt < 4; nt++) {
                float p0 = __expf(sacc[nt][0]);
                float p1 = __expf(sacc[nt][1]);
                float p2 = __expf(sacc[nt][2]);
                float p3 = __expf(sacc[nt][3]);
                rs0 += p0 + p1; rs1 += p2 + p3;
                sacc[nt][0] = f2tf32(p0); sacc[nt][1] = f2tf32(p1);
                sacc[nt][2] = f2tf32(p2); sacc[nt][3] = f2tf32(p3);
            }
            rs0 += __shfl_xor_sync(0xFFFFFFFFu, rs0, 1);
            rs0 += __shfl_xor_sync(0xFFFFFFFFu, rs0, 2);
            rs1 += __shfl_xor_sync(0xFFFFFFFFu, rs1, 1);
            rs1 += __shfl_xor_sync(0xFFFFFFFFu, rs1, 2);
            l0 += rs0; l1 += rs1;
        }

        // ---- O += P V : P accumulators feed A directly (kv relabeled by perm8) ----
        #pragma unroll
        for (int kc = 0; kc < 4; kc++) {
            uint32_t a[4] = { __float_as_uint(sacc[kc][0]),
                              __float_as_uint(sacc[kc][2]),
                              __float_as_uint(sacc[kc][1]),
                              __float_as_uint(sacc[kc][3]) };
            #pragma unroll
            for (int nt = 0; nt < 8; nt++) {
                float2 vf = *(const float2*)(Vb + (nt * 8 + group) * VPITCH + kc * 8 + tg * 2);
                mma_tf32(oacc[nt], a, __float_as_uint(vf.x), __float_as_uint(vf.y));
            }
        }

        __syncthreads();
        if (t + 2 < NTILES) prefetch(t + 2, buf);
    }

    // ---- finalize: write g_attn tf32-rounded with perm32 K-layout (for proj GEMM) ----
    float inv0 = 1.f / l0, inv1 = 1.f / l1;
    int tok0 = qtile * QR + warp * 16 + group;
    float* or0 = aout + ((size_t)(bB * Nv + tok0)) * Cv + h * Dv;
    float* or1 = or0 + 8 * (size_t)Cv;
    #pragma unroll
    for (int nt = 0; nt < 8; nt++) {
        int cA = perm32(nt * 8 + 2 * tg);
        int cB = perm32(nt * 8 + 2 * tg + 1);
        or0[cA] = f2tf32(oacc[nt][0] * inv0);
        or0[cB] = f2tf32(oacc[nt][1] * inv0);
        or1[cA] = f2tf32(oacc[nt][2] * inv1);
        or1[cB] = f2tf32(oacc[nt][3] * inv1);
    }
}

// ---------------- launch ----------------
extern "C" void kernel_launch(void* const* d_in, const int* in_sizes, int n_in,
                              void* d_out, int out_size)
{
    const float* x            = (const float*)d_in[0];
    const unsigned char* mask = (const unsigned char*)d_in[1];
    const float* w_qkv        = (const float*)d_in[2];
    const float* w_proj       = (const float*)d_in[3];
    const float* b_proj       = (const float*)d_in[4];
    const float* qg           = (const float*)d_in[5];
    const float* qb           = (const float*)d_in[6];
    const float* kg           = (const float*)d_in[7];
    const float* kb           = (const float*)d_in[8];
    float* out                = (float*)d_out;

    void *pq, *pk, *pv, *pa, *pf, *pxr, *pwq, *pwp;
    cudaGetSymbolAddress(&pq, g_q);
    cudaGetSymbolAddress(&pk, g_k);
    cudaGetSymbolAddress(&pv, g_v);
    cudaGetSymbolAddress(&pa, g_attn);
    cudaGetSymbolAddress(&pf, g_maskflag);
    cudaGetSymbolAddress(&pxr, g_xr);
    cudaGetSymbolAddress(&pwq, g_wqkvr);
    cudaGetSymbolAddress(&pwp, g_wprojr);
    float* q = (float*)pq; float* k = (float*)pk; float* v = (float*)pv;
    float* attn = (float*)pa; int* flag = (int*)pf;
    float* xr = (float*)pxr; float* wqkvr = (float*)pwq; float* wprojr = (float*)pwp;

    const int FLASH_SMEM = FLASH_SMEM_F * 4;   // 57344 B -> 4 CTAs/SM
    cudaFuncSetAttribute(flash_kernel<false>, cudaFuncAttributeMaxDynamicSharedMemorySize, FLASH_SMEM);
    cudaFuncSetAttribute(flash_kernel<true>,  cudaFuncAttributeMaxDynamicSharedMemorySize, FLASH_SMEM);
    cudaFuncSetAttribute(gemm_tc_async<EpiQKV>, cudaFuncAttributeMaxDynamicSharedMemorySize, GEMM_SMEM);
    cudaFuncSetAttribute(gemm_tc_async<EpiOut>, cudaFuncAttributeMaxDynamicSharedMemorySize, GEMM_SMEM);

    // 0) mask any-true flag
    cudaMemsetAsync(flag, 0, sizeof(int));
    mask_any_kernel<<<512, 256>>>((const uint4*)mask, (Bv*Nv*Nv)/16, flag);

    // 0b) pre-round + perm32 K-interleave x, w_qkv, w_proj
    round_perm_kernel<<<1024, 256>>>((const float4*)x,      (float4*)xr,     MROWS*Cv/32);
    round_perm_kernel<<<1024, 256>>>((const float4*)w_qkv,  (float4*)wqkvr,  C3*Cv/32);
    round_perm_kernel<<<512,  256>>>((const float4*)w_proj, (float4*)wprojr, Cv*Cv/32);

    // 1) QKV projection with FUSED per-head LayerNorm in the epilogue
    {
        EpiQKV epi{q, k, v, qg, qb, kg, kb};
        dim3 grid(C3/128, MROWS/128, 1);
        gemm_tc_async<EpiQKV><<<grid, 256, GEMM_SMEM>>>(xr, wqkvr, Cv, 0, 0, epi);
    }
    // 2) fused attention (one of the two instances self-selects on the flag)
    {
        dim3 grid(Nv/QR, BHv);
        flash_kernel<false><<<grid, 128, FLASH_SMEM>>>(q, k, v, mask, flag, attn);
        flash_kernel<true><<<grid, 128, FLASH_SMEM>>>(q, k, v, mask, flag, attn);
    }
    // 3) out = attn @ w_proj^T + b_proj (async pipelined GEMM)
    {
        EpiOut epi{out, b_proj};
        dim3 grid(Cv/128, MROWS/128, 1);
        gemm_tc_async<EpiOut><<<grid, 256, GEMM_SMEM>>>(attn, wprojr, Cv, 0, 0, epi);
    }
}

// round 17
// speedup vs baseline: 1.1410x; 1.1410x over previous
#include <cuda_runtime.h>
#include <math.h>
#include <float.h>
#include <stdint.h>

// Problem constants
#define Bv 2
#define Nv 2048
#define Cv 1024
#define Hv 16
#define Dv 64
#define BHv (Bv*Hv)        // 32
#define MROWS (Bv*Nv)      // 4096
#define C3 (3*Cv)          // 3072

// Static device scratch (allocation-free rule)
__device__ float g_q[BHv*Nv*Dv];            // [b,h,n,d] (d interleaved perm8)
__device__ float g_k[BHv*Nv*Dv];            // [b,h,n,d] (d interleaved perm8)
__device__ float g_v[BHv*Nv*Dv];            // [b,h,d,n] transposed, natural token order
__device__ float g_attn[MROWS*Cv];          // [b*n, h*d], tf32-rounded + perm8 K-layout
__device__ float g_xr[MROWS*Cv];            // x, tf32-rounded + perm8
__device__ float g_wqkvr[C3*Cv];            // w_qkv, rounded + perm8
__device__ float g_wprojr[Cv*Cv];           // w_proj, rounded + perm8
__device__ int   g_maskflag;

// ---------------- tf32 helpers ----------------
__device__ __forceinline__ float f2tf32(float x) {
    uint32_t u;
    asm("cvt.rna.tf32.f32 %0, %1;" : "=r"(u) : "f"(x));
    return __uint_as_float(u);
}

__device__ __forceinline__ void mma_tf32(float* c, const uint32_t* a, uint32_t b0, uint32_t b1) {
    asm volatile(
        "mma.sync.aligned.m16n8k8.row.col.f32.tf32.tf32.f32 "
        "{%0,%1,%2,%3}, {%4,%5,%6,%7}, {%8,%9}, {%0,%1,%2,%3};\n"
        : "+f"(c[0]), "+f"(c[1]), "+f"(c[2]), "+f"(c[3])
        : "r"(a[0]), "r"(a[1]), "r"(a[2]), "r"(a[3]), "r"(b0), "r"(b1));
}

__device__ __forceinline__ void cp16(uint32_t dst, const void* src) {
    asm volatile("cp.async.cg.shared.global [%0], [%1], 16;\n" :: "r"(dst), "l"(src));
}

// interleave within 8-blocks: orig j -> pos ((j&3)<<1)|(j>>2)
__device__ __forceinline__ int perm8(int j) { return ((j & 3) << 1) | (j >> 2); }

// ---------------- pre-round + perm8 K-interleave, 3 tensors in one launch ----------------
__global__ void round_perm3_kernel(const float4* __restrict__ s0, float2* __restrict__ d0, int n0,
                                   const float4* __restrict__ s1, float2* __restrict__ d1, int n1,
                                   const float4* __restrict__ s2, float2* __restrict__ d2, int n2)
{
    int total = n0 + n1 + n2;
    for (int i = blockIdx.x * blockDim.x + threadIdx.x; i < total; i += gridDim.x * blockDim.x) {
        const float4* in; float2* out; int j = i;
        if (j < n0)            { in = s0; out = d0; }
        else if ((j -= n0) < n1) { in = s1; out = d1; }
        else                   { j -= n1; in = s2; out = d2; }
        float4 a = in[2*j], b = in[2*j+1];   // orig cols 0-3, 4-7 of this 8-block
        out[4*j+0] = make_float2(f2tf32(a.x), f2tf32(b.x));
        out[4*j+1] = make_float2(f2tf32(a.y), f2tf32(b.y));
        out[4*j+2] = make_float2(f2tf32(a.z), f2tf32(b.z));
        out[4*j+3] = make_float2(f2tf32(a.w), f2tf32(b.w));
    }
}

// ---------------- Epilogue policies (warp-level store) ----------------
// acc layout: acc[mt][nt][r] -> row (bm + wm*32 + mt*16 + group) for r=0,1,
//             row +8 for r=2,3; col (bn + wn*64 + nt*8 + tg*2 + (r&1)).
struct EpiQKV {
    float *q, *k, *v;
    const float *qg, *qb, *kg, *kb;
    __device__ __forceinline__ void store(int bz, int bm, int bn, int wm, int wn,
                                          int group, int tg,
                                          const float (&acc)[2][8][4]) const {
        const int ncol0 = bn + wn * 64;      // aligned 64-block: one (which, head)
        const int which = ncol0 >> 10;
        const int h     = (ncol0 & 1023) >> 6;
        if (which == 2) {
            // ---- V: transposed [b,h][d][n], natural token order, tf32 ----
            #pragma unroll
            for (int mt = 0; mt < 2; mt++) {
                int m0 = bm + wm * 32 + mt * 16 + group;
                int b0 = m0 >> 11, t0 = m0 & 2047;
                int m1 = m0 + 8;
                int b1 = m1 >> 11, t1 = m1 & 2047;
                float* base0 = v + (((size_t)(b0 * Hv + h) * Dv) << 11) + t0;
                float* base1 = v + (((size_t)(b1 * Hv + h) * Dv) << 11) + t1;
                #pragma unroll
                for (int nt = 0; nt < 8; nt++) {
                    int dd = nt * 8 + tg * 2;
                    base0[(size_t)dd << 11]       = f2tf32(acc[mt][nt][0]);
                    base0[(size_t)(dd + 1) << 11] = f2tf32(acc[mt][nt][1]);
                    base1[(size_t)dd << 11]       = f2tf32(acc[mt][nt][2]);
                    base1[(size_t)(dd + 1) << 11] = f2tf32(acc[mt][nt][3]);
                }
            }
        } else {
            // ---- q/k: fused LayerNorm over the 64 cols (quad-distributed), perm8 store ----
            const float* G  = which ? kg : qg;
            const float* Bt = which ? kb : qb;
            float* dst = which ? k : q;
            const int pa = perm8(2 * tg), pb = perm8(2 * tg + 1);
            #pragma unroll
            for (int mt = 0; mt < 2; mt++) {
                float sA = 0.f, sB = 0.f;
                #pragma unroll
                for (int nt = 0; nt < 8; nt++) {
                    sA += acc[mt][nt][0] + acc[mt][nt][1];
                    sB += acc[mt][nt][2] + acc[mt][nt][3];
                }
                sA += __shfl_xor_sync(0xFFFFFFFFu, sA, 1);
                sA += __shfl_xor_sync(0xFFFFFFFFu, sA, 2);
                sB += __shfl_xor_sync(0xFFFFFFFFu, sB, 1);
                sB += __shfl_xor_sync(0xFFFFFFFFu, sB, 2);
                float muA = sA * (1.f/64.f), muB = sB * (1.f/64.f);
                float vA = 0.f, vB = 0.f;
                #pragma unroll
                for (int nt = 0; nt < 8; nt++) {
                    float d0 = acc[mt][nt][0] - muA, d1 = acc[mt][nt][1] - muA;
                    float d2 = acc[mt][nt][2] - muB, d3 = acc[mt][nt][3] - muB;
                    vA += d0*d0 + d1*d1;
                    vB += d2*d2 + d3*d3;
                }
                vA += __shfl_xor_sync(0xFFFFFFFFu, vA, 1);
                vA += __shfl_xor_sync(0xFFFFFFFFu, vA, 2);
                vB += __shfl_xor_sync(0xFFFFFFFFu, vB, 1);
                vB += __shfl_xor_sync(0xFFFFFFFFu, vB, 2);
                float invA = rsqrtf(vA * (1.f/64.f) + 1e-5f);
                float invB = rsqrtf(vB * (1.f/64.f) + 1e-5f);

                int m0 = bm + wm * 32 + mt * 16 + group;
                int b0 = m0 >> 11, t0 = m0 & 2047;
                int m1 = m0 + 8;
                int b1 = m1 >> 11, t1 = m1 & 2047;
                float* r0 = dst + (((size_t)(b0 * Hv + h) * Nv + t0) << 6);
                float* r1 = dst + (((size_t)(b1 * Hv + h) * Nv + t1) << 6);
                #pragma unroll
                for (int nt = 0; nt < 8; nt++) {
                    int dd = nt * 8 + tg * 2;
                    float g0 = G[dd], g1 = G[dd + 1];
                    float bt0 = Bt[dd], bt1 = Bt[dd + 1];
                    r0[nt*8 + pa] = f2tf32((acc[mt][nt][0] - muA) * invA * g0 + bt0);
                    r0[nt*8 + pb] = f2tf32((acc[mt][nt][1] - muA) * invA * g1 + bt1);
                    r1[nt*8 + pa] = f2tf32((acc[mt][nt][2] - muB) * invB * g0 + bt0);
                    r1[nt*8 + pb] = f2tf32((acc[mt][nt][3] - muB) * invB * g1 + bt1);
                }
            }
        }
    }
};

struct EpiOut {
    float* out;
    const float* bias;
    __device__ __forceinline__ void store(int bz, int bm, int bn, int wm, int wn,
                                          int group, int tg,
                                          const float (&acc)[2][8][4]) const {
        #pragma unroll
        for (int mt = 0; mt < 2; mt++) {
            int r0 = bm + wm * 32 + mt * 16 + group;
            #pragma unroll
            for (int nt = 0; nt < 8; nt++) {
                int c0 = bn + wn * 64 + nt * 8 + tg * 2;
                out[(size_t)r0 * Cv + c0]           = acc[mt][nt][0] + bias[c0];
                out[(size_t)r0 * Cv + c0 + 1]       = acc[mt][nt][1] + bias[c0 + 1];
                out[(size_t)(r0 + 8) * Cv + c0]     = acc[mt][nt][2] + bias[c0];
                out[(size_t)(r0 + 8) * Cv + c0 + 1] = acc[mt][nt][3] + bias[c0 + 1];
            }
        }
    }
};

// ============ async tf32 GEMM, TN, operands pre-rounded + perm8 K-interleaved ============
// C = A(MxK,rm) * B(NxK,rm)^T.  BM=BN=128, BK=32, 256 threads, 2-stage cp.async.
// GP=40: half-warp LDS.64 banks = (8g+2tg) mod 32 -> conflict-free.
#define GP 40                       // smem pitch (floats)
#define GASZ (128*GP)               // one stage of one operand (5120 floats)
template<class Epi>
__global__ void __launch_bounds__(256, 2)
gemm_tc_async(const float* __restrict__ A, const float* __restrict__ B,
              int K, long long sA, long long sB, Epi epi)
{
    constexpr int BM = 128, BN = 128, BK = 32, WM = 32, WN = 64;
    constexpr int WARPS_N = BN / WN;          // 2
    constexpr int MT = WM / 16, NT = WN / 8;  // 2, 8

    extern __shared__ float sg[];             // [A0][A1][B0][B1], each GASZ floats
    const int bz = blockIdx.z;
    A += (long long)bz * sA + (long long)blockIdx.y * BM * K;
    B += (long long)bz * sB + (long long)blockIdx.x * BN * K;
    const int tid  = threadIdx.x;
    const int warp = tid >> 5, lane = tid & 31;
    const int wm = warp / WARPS_N, wn = warp % WARPS_N;
    const int group = lane >> 2, tg = lane & 3;
    uint32_t sb = (uint32_t)__cvta_generic_to_shared(sg);

    auto prefetch = [&](int k0, int s) {
        #pragma unroll
        for (int j = 0; j < 4; j++) {
            int i = tid + j * 256;
            int m = i >> 3, kv = i & 7;       // 128 rows x 8 float4
            cp16(sb + (uint32_t)((s * GASZ + m * GP + kv * 4) * 4),
                 A + (long long)m * K + k0 + kv * 4);
            cp16(sb + (uint32_t)(((2 + s) * GASZ + m * GP + kv * 4) * 4),
                 B + (long long)m * K + k0 + kv * 4);
        }
        asm volatile("cp.async.commit_group;\n" ::: "memory");
    };

    float acc[MT][NT][4];
    #pragma unroll
    for (int i = 0; i < MT; i++)
        #pragma unroll
        for (int j = 0; j < NT; j++)
            #pragma unroll
            for (int r = 0; r < 4; r++) acc[i][j][r] = 0.f;

    const int nk = K / BK;
    prefetch(0, 0);
    prefetch(BK, 1);

    for (int kt = 0; kt < nk; kt++) {
        const int s = kt & 1;
        if (kt < nk - 1) asm volatile("cp.async.wait_group 1;\n" ::: "memory");
        else             asm volatile("cp.async.wait_group 0;\n" ::: "memory");
        __syncthreads();

        const float* As = sg + s * GASZ;
        const float* Bs = sg + (2 + s) * GASZ;

        #pragma unroll
        for (int kk = 0; kk < BK; kk += 8) {
            uint32_t af[MT][4], bf[NT][2];
            #pragma unroll
            for (int mt = 0; mt < MT; mt++) {
                int r = wm * WM + mt * 16 + group;
                float2 f0 = *(const float2*)(As + r * GP + kk + 2 * tg);
                float2 f1 = *(const float2*)(As + (r + 8) * GP + kk + 2 * tg);
                af[mt][0] = __float_as_uint(f0.x);
                af[mt][1] = __float_as_uint(f1.x);
                af[mt][2] = __float_as_uint(f0.y);
                af[mt][3] = __float_as_uint(f1.y);
            }
            #pragma unroll
            for (int nt = 0; nt < NT; nt++) {
                int c = wn * WN + nt * 8 + group;
                float2 g2 = *(const float2*)(Bs + c * GP + kk + 2 * tg);
                bf[nt][0] = __float_as_uint(g2.x);
                bf[nt][1] = __float_as_uint(g2.y);
            }
            #pragma unroll
            for (int mt = 0; mt < MT; mt++)
                #pragma unroll
                for (int nt = 0; nt < NT; nt++)
                    mma_tf32(acc[mt][nt], af[mt], bf[nt][0], bf[nt][1]);
        }
        __syncthreads();
        if (kt + 2 < nk) prefetch((kt + 2) * BK, s);
    }

    epi.store(bz, blockIdx.y * BM, blockIdx.x * BN, wm, wn, group, tg, acc);
}
#define GEMM_SMEM (4*GASZ*4)        // 81920 bytes -> 2 CTAs/SM

// ---------------- mask any-true scan ----------------
__global__ void mask_any_kernel(const uint4* __restrict__ m, int n4, int* flag)
{
    int i = blockIdx.x * blockDim.x + threadIdx.x;
    bool any = false;
    for (; i < n4; i += gridDim.x * blockDim.x) {
        uint4 t = m[i];
        any |= ((t.x | t.y | t.z | t.w) != 0u);
    }
    if (__syncthreads_or(any)) {
        if (threadIdx.x == 0) atomicOr(flag, 1);
    }
}

// ================= fused flash attention =================
// CTA: 128 threads (4 warps, 64 q-rows). KV tile 32 tokens, double-buffered.
// PV uses kv relabeling sigma=perm8: P accumulators feed mma A directly, no shuffles.
#define QR 64
#define KT 32
#define PITCH 72            // Q/K row pitch (floats)
#define VPITCH 40           // V^T row pitch (floats)
#define QTILEF (QR*PITCH)   // 4608
#define KTILEF (KT*PITCH)   // 2304
#define VTILEF (Dv*VPITCH)  // 2560
#define OFF_K0 QTILEF
#define OFF_K1 (QTILEF + KTILEF)
#define OFF_V0 (QTILEF + 2*KTILEF)
#define OFF_V1 (QTILEF + 2*KTILEF + VTILEF)
#define FLASH_SMEM_F (QTILEF + 2*KTILEF + 2*VTILEF)   // 14336 floats = 57344 B

template<bool MASKED>
__global__ void __launch_bounds__(128, 4)
flash_kernel(const float* __restrict__ q, const float* __restrict__ k,
             const float* __restrict__ v, const unsigned char* __restrict__ mask,
             const int* __restrict__ maskflag, float* __restrict__ aout)
{
    const int mf = *maskflag;
    if (MASKED ? (mf == 0) : (mf != 0)) return;   // exactly one instance runs

    extern __shared__ float sm[];
    const int tid  = threadIdx.x;
    const int warp = tid >> 5, lane = tid & 31;
    const int group = lane >> 2, tg = lane & 3;
    const int qtile = blockIdx.x;
    const int bh = blockIdx.y;
    const int bB = bh >> 4, h = bh & 15;

    const float* qbase = q + (size_t)bh * Nv * Dv + (size_t)qtile * QR * Dv;
    const float* kbase = k + (size_t)bh * Nv * Dv;
    const float* vbase = v + (size_t)bh * Nv * Dv;      // [d][n] layout
    uint32_t sbase = (uint32_t)__cvta_generic_to_shared(sm);

    // ---- stage Q tile (pre-scaled by d^-1/2) ----
    #pragma unroll
    for (int i = 0; i < 8; i++) {
        int idx = tid + i * 128;              // 64 rows x 16 float4
        int row = idx >> 4, c4 = (idx & 15) * 4;
        float4 t = *(const float4*)(qbase + row * Dv + c4);
        t.x *= 0.125f; t.y *= 0.125f; t.z *= 0.125f; t.w *= 0.125f;
        *(float4*)(sm + row * PITCH + c4) = t;
    }
    __syncthreads();

    auto prefetch = [&](int t, int b) {
        const float* kb = kbase + (size_t)t * KT * Dv;
        const float* vb = vbase + (size_t)t * KT;       // column block of V^T
        uint32_t kd = sbase + (uint32_t)((b ? OFF_K1 : OFF_K0)) * 4u;
        uint32_t vd = sbase + (uint32_t)((b ? OFF_V1 : OFF_V0)) * 4u;
        #pragma unroll
        for (int i = 0; i < 4; i++) {
            int idx = tid + i * 128;
            {   // K: 32 rows x 16 float4
                int row = idx >> 4, c4 = (idx & 15) * 4;
                cp16(kd + (row * PITCH + c4) * 4, kb + row * Dv + c4);
            }
            {   // V^T: 64 rows x 8 float4
                int row = idx >> 3, c4 = (idx & 7) * 4;
                cp16(vd + (row * VPITCH + c4) * 4, vb + (size_t)row * Nv + c4);
            }
        }
        asm volatile("cp.async.commit_group;\n" ::: "memory");
    };

    prefetch(0, 0);
    prefetch(1, 1);

    // ---- running state ----
    float m0 = -FLT_MAX, m1 = -FLT_MAX, l0 = 0.f, l1 = 0.f;
    float oacc[8][4];
    #pragma unroll
    for (int i = 0; i < 8; i++)
        #pragma unroll
        for (int j = 0; j < 4; j++) oacc[i][j] = 0.f;

    const int NTILES = Nv / KT;               // 64
    const float* Qr0 = sm + (warp * 16 + group) * PITCH + tg * 2;
    const float* Qr1 = Qr0 + 8 * PITCH;

    for (int t = 0; t < NTILES; t++) {
        const int buf = t & 1;
        if (t < NTILES - 1) asm volatile("cp.async.wait_group 1;\n" ::: "memory");
        else                asm volatile("cp.async.wait_group 0;\n" ::: "memory");
        __syncthreads();

        const float* Kb = sm + (buf ? OFF_K1 : OFF_K0);
        const float* Vb = sm + (buf ? OFF_V1 : OFF_V0);

        // ---- S = Q K^T (16 x 32 per warp), LDS.64 fragments ----
        float sacc[4][4];
        #pragma unroll
        for (int nt = 0; nt < 4; nt++)
            #pragma unroll
            for (int r = 0; r < 4; r++) sacc[nt][r] = 0.f;

        #pragma unroll
        for (int kk = 0; kk < 8; kk++) {
            float2 qa = *(const float2*)(Qr0 + kk * 8);
            float2 qb = *(const float2*)(Qr1 + kk * 8);
            uint32_t a[4] = { __float_as_uint(qa.x), __float_as_uint(qb.x),
                              __float_as_uint(qa.y), __float_as_uint(qb.y) };
            #pragma unroll
            for (int nt = 0; nt < 4; nt++) {
                float2 kf = *(const float2*)(Kb + (nt * 8 + group) * PITCH + kk * 8 + tg * 2);
                mma_tf32(sacc[nt], a, __float_as_uint(kf.x), __float_as_uint(kf.y));
            }
        }

        float rs0 = 0.f, rs1 = 0.f;
        if (MASKED) {
            // ---- mask + full online softmax (general path) ----
            const unsigned char* mr0 = mask + ((size_t)(bB * Nv + qtile*QR + warp*16 + group)) * Nv + t * KT;
            const unsigned char* mr1 = mr0 + 8 * Nv;
            #pragma unroll
            for (int nt = 0; nt < 4; nt++) {
                int c = nt * 8 + 2 * tg;
                if (mr0[c])     sacc[nt][0] = -FLT_MAX;
                if (mr0[c + 1]) sacc[nt][1] = -FLT_MAX;
                if (mr1[c])     sacc[nt][2] = -FLT_MAX;
                if (mr1[c + 1]) sacc[nt][3] = -FLT_MAX;
            }
            float mn0 = -FLT_MAX, mn1 = -FLT_MAX;
            #pragma unroll
            for (int nt = 0; nt < 4; nt++) {
                mn0 = fmaxf(mn0, fmaxf(sacc[nt][0], sacc[nt][1]));
                mn1 = fmaxf(mn1, fmaxf(sacc[nt][2], sacc[nt][3]));
            }
            mn0 = fmaxf(mn0, __shfl_xor_sync(0xFFFFFFFFu, mn0, 1));
            mn0 = fmaxf(mn0, __shfl_xor_sync(0xFFFFFFFFu, mn0, 2));
            mn1 = fmaxf(mn1, __shfl_xor_sync(0xFFFFFFFFu, mn1, 1));
            mn1 = fmaxf(mn1, __shfl_xor_sync(0xFFFFFFFFu, mn1, 2));
            float mt0 = fmaxf(m0, mn0), mt1 = fmaxf(m1, mn1);
            #pragma unroll
            for (int nt = 0; nt < 4; nt++) {
                float p0 = __expf(sacc[nt][0] - mt0);
                float p1 = __expf(sacc[nt][1] - mt0);
                float p2 = __expf(sacc[nt][2] - mt1);
                float p3 = __expf(sacc[nt][3] - mt1);
                rs0 += p0 + p1; rs1 += p2 + p3;
                sacc[nt][0] = f2tf32(p0); sacc[nt][1] = f2tf32(p1);
                sacc[nt][2] = f2tf32(p2); sacc[nt][3] = f2tf32(p3);
            }
            rs0 += __shfl_xor_sync(0xFFFFFFFFu, rs0, 1);
            rs0 += __shfl_xor_sync(0xFFFFFFFFu, rs0, 2);
            rs1 += __shfl_xor_sync(0xFFFFFFFFu, rs1, 1);
            rs1 += __shfl_xor_sync(0xFFFFFFFFu, rs1, 2);
            if (__any_sync(0xFFFFFFFFu, (mn0 > m0) | (mn1 > m1))) {
                float a0 = __expf(m0 - mt0), a1 = __expf(m1 - mt1);
                l0 = a0 * l0 + rs0;
                l1 = a1 * l1 + rs1;
                #pragma unroll
                for (int i = 0; i < 8; i++) {
                    oacc[i][0] *= a0; oacc[i][1] *= a0;
                    oacc[i][2] *= a1; oacc[i][3] *= a1;
                }
            } else {
                l0 += rs0; l1 += rs1;
            }
            m0 = mt0; m1 = mt1;
        } else {
            // ---- fixed-max softmax: LN bounds |S| <= 8, exp directly.
            // P fed to tf32 mma as raw fp32 (HW truncates to tf32) -> no cvt.
            #pragma unroll
            for (int nt = 0; nt < 4; nt++) {
                float p0 = __expf(sacc[nt][0]);
                float p1 = __expf(sacc[nt][1]);
                float p2 = __expf(sacc[nt][2]);
                float p3 = __expf(sacc[nt][3]);
                rs0 += p0 + p1; rs1 += p2 + p3;
                sacc[nt][0] = p0; sacc[nt][1] = p1;
                sacc[nt][2] = p2; sacc[nt][3] = p3;
            }
            rs0 += __shfl_xor_sync(0xFFFFFFFFu, rs0, 1);
            rs0 += __shfl_xor_sync(0xFFFFFFFFu, rs0, 2);
            rs1 += __shfl_xor_sync(0xFFFFFFFFu, rs1, 1);
            rs1 += __shfl_xor_sync(0xFFFFFFFFu, rs1, 2);
            l0 += rs0; l1 += rs1;
        }

        // ---- O += P V : P accumulators feed A directly (kv relabeled by perm8) ----
        #pragma unroll
        for (int kc = 0; kc < 4; kc++) {
            uint32_t a[4] = { __float_as_uint(sacc[kc][0]),
                              __float_as_uint(sacc[kc][2]),
                              __float_as_uint(sacc[kc][1]),
                              __float_as_uint(sacc[kc][3]) };
            #pragma unroll
            for (int nt = 0; nt < 8; nt++) {
                float2 vf = *(const float2*)(Vb + (nt * 8 + group) * VPITCH + kc * 8 + tg * 2);
                mma_tf32(oacc[nt], a, __float_as_uint(vf.x), __float_as_uint(vf.y));
            }
        }

        __syncthreads();
        if (t + 2 < NTILES) prefetch(t + 2, buf);
    }

    // ---- finalize: write g_attn tf32-rounded AND perm8 K-interleaved (for proj GEMM) ----
    float inv0 = 1.f / l0, inv1 = 1.f / l1;
    int tok0 = qtile * QR + warp * 16 + group;
    float* or0 = aout + ((size_t)(bB * Nv + tok0)) * Cv + h * Dv;
    float* or1 = or0 + 8 * (size_t)Cv;
    const int pA = perm8(2 * tg), pB = perm8(2 * tg + 1);
    #pragma unroll
    for (int nt = 0; nt < 8; nt++) {
        int cA = nt * 8 + pA, cB = nt * 8 + pB;
        or0[cA] = f2tf32(oacc[nt][0] * inv0);
        or0[cB] = f2tf32(oacc[nt][1] * inv0);
        or1[cA] = f2tf32(oacc[nt][2] * inv1);
        or1[cB] = f2tf32(oacc[nt][3] * inv1);
    }
}

// ---------------- launch ----------------
extern "C" void kernel_launch(void* const* d_in, const int* in_sizes, int n_in,
                              void* d_out, int out_size)
{
    const float* x            = (const float*)d_in[0];
    const unsigned char* mask = (const unsigned char*)d_in[1];
    const float* w_qkv        = (const float*)d_in[2];
    const float* w_proj       = (const float*)d_in[3];
    const float* b_proj       = (const float*)d_in[4];
    const float* qg           = (const float*)d_in[5];
    const float* qb           = (const float*)d_in[6];
    const float* kg           = (const float*)d_in[7];
    const float* kb           = (const float*)d_in[8];
    float* out                = (float*)d_out;

    void *pq, *pk, *pv, *pa, *pf, *pxr, *pwq, *pwp;
    cudaGetSymbolAddress(&pq, g_q);
    cudaGetSymbolAddress(&pk, g_k);
    cudaGetSymbolAddress(&pv, g_v);
    cudaGetSymbolAddress(&pa, g_attn);
    cudaGetSymbolAddress(&pf, g_maskflag);
    cudaGetSymbolAddress(&pxr, g_xr);
    cudaGetSymbolAddress(&pwq, g_wqkvr);
    cudaGetSymbolAddress(&pwp, g_wprojr);
    float* q = (float*)pq; float* k = (float*)pk; float* v = (float*)pv;
    float* attn = (float*)pa; int* flag = (int*)pf;
    float* xr = (float*)pxr; float* wqkvr = (float*)pwq; float* wprojr = (float*)pwp;

    const int FLASH_SMEM = FLASH_SMEM_F * 4;   // 57344 B -> 4 CTAs/SM
    cudaFuncSetAttribute(flash_kernel<false>, cudaFuncAttributeMaxDynamicSharedMemorySize, FLASH_SMEM);
    cudaFuncSetAttribute(flash_kernel<true>,  cudaFuncAttributeMaxDynamicSharedMemorySize, FLASH_SMEM);
    cudaFuncSetAttribute(gemm_tc_async<EpiQKV>, cudaFuncAttributeMaxDynamicSharedMemorySize, GEMM_SMEM);
    cudaFuncSetAttribute(gemm_tc_async<EpiOut>, cudaFuncAttributeMaxDynamicSharedMemorySize, GEMM_SMEM);

    // 0) mask any-true flag
    cudaMemsetAsync(flag, 0, sizeof(int));
    mask_any_kernel<<<512, 256>>>((const uint4*)mask, (Bv*Nv*Nv)/16, flag);

    // 0b) pre-round + perm8 K-interleave x, w_qkv, w_proj in ONE launch
    round_perm3_kernel<<<2048, 256>>>(
        (const float4*)x,      (float2*)xr,     MROWS*Cv/8,
        (const float4*)w_qkv,  (float2*)wqkvr,  C3*Cv/8,
        (const float4*)w_proj, (float2*)wprojr, Cv*Cv/8);

    // 1) QKV projection with FUSED per-head LayerNorm in the epilogue
    {
        EpiQKV epi{q, k, v, qg, qb, kg, kb};
        dim3 grid(C3/128, MROWS/128, 1);
        gemm_tc_async<EpiQKV><<<grid, 256, GEMM_SMEM>>>(xr, wqkvr, Cv, 0, 0, epi);
    }
    // 2) fused attention (one of the two instances self-selects on the flag)
    {
        dim3 grid(Nv/QR, BHv);
        flash_kernel<false><<<grid, 128, FLASH_SMEM>>>(q, k, v, mask, flag, attn);
        flash_kernel<true><<<grid, 128, FLASH_SMEM>>>(q, k, v, mask, flag, attn);
    }
    // 3) out = attn @ w_proj^T + b_proj (async pipelined GEMM)
    {
        EpiOut epi{out, b_proj};
        dim3 grid(Cv/128, MROWS/128, 1);
        gemm_tc_async<EpiOut><<<grid, 256, GEMM_SMEM>>>(attn, wprojr, Cv, 0, 0, epi);
    }
}